// round 14
// baseline (speedup 1.0000x reference)
#include <cuda_runtime.h>

#define BB 16
#define NN 2048
#define KK 10
#define FULLM 0xffffffffu
#define NCHUNK (NN / 32)          // 64

__device__ int      g_idx[BB * NN * KK];
__device__ float    g_loss[BB * NN];
__device__ float4   g_sorted[BB * NN];
__device__ int      g_sidx[BB * NN];
__device__ float4   g_blo[BB * NCHUNK];
__device__ float4   g_bhi[BB * NCHUNK];
__device__ unsigned g_min[BB];
__device__ int      g_cnt[BB];

__device__ __forceinline__ unsigned expand10(unsigned v) {
    v &= 1023u;
    v = (v | (v << 16)) & 0x030000FFu;
    v = (v | (v << 8))  & 0x0300F00Fu;
    v = (v | (v << 4))  & 0x030C30C3u;
    v = (v | (v << 2))  & 0x09249249u;
    return v;
}

// ---------------------------------------------------------------------------
// Kernel 0: per-batch bitonic sort of points by MORTON code. Emits sorted
// (x,y,z,|p|^2), original indices, exact per-chunk AABBs. Inits g_min/g_cnt.
// ---------------------------------------------------------------------------
__global__ void __launch_bounds__(1024) sort_kernel(const float* __restrict__ src) {
    __shared__ unsigned skey[NN];
    __shared__ int      sval[NN];
    __shared__ float    sx[NN], sy[NN], sz[NN];
    const int b = blockIdx.x;
    const float* base = src + (size_t)b * 3 * NN;
    if (threadIdx.x == 0) { g_min[b] = 0x7f800000u; g_cnt[b] = 0; }

    for (int i = threadIdx.x; i < NN; i += 1024) {
        float x = base[i], y = base[NN + i], z = base[2 * NN + i];
        int qxi = (int)((x + 8.0f) * 64.0f);
        int qyi = (int)((y + 8.0f) * 64.0f);
        int qzi = (int)((z + 8.0f) * 64.0f);
        qxi = min(max(qxi, 0), 1023);
        qyi = min(max(qyi, 0), 1023);
        qzi = min(max(qzi, 0), 1023);
        skey[i] = (expand10((unsigned)qxi) << 2) |
                  (expand10((unsigned)qyi) << 1) |
                   expand10((unsigned)qzi);
        sval[i] = i;
    }

    for (int k = 2; k <= NN; k <<= 1) {
        for (int j = k >> 1; j > 0; j >>= 1) {
            __syncthreads();
            const int t   = threadIdx.x;
            const int i   = 2 * t - (t & (j - 1));
            const int ixj = i + j;
            const bool up = ((i & k) == 0);
            unsigned a = skey[i], c = skey[ixj];
            if ((a > c) == up) {
                skey[i] = c; skey[ixj] = a;
                int v = sval[i]; sval[i] = sval[ixj]; sval[ixj] = v;
            }
        }
    }
    __syncthreads();

    for (int i = threadIdx.x; i < NN; i += 1024) {
        int orig = sval[i];
        float x = base[orig];
        float y = base[NN + orig];
        float z = base[2 * NN + orig];
        g_sorted[b * NN + i] = make_float4(x, y, z, x * x + y * y + z * z);
        g_sidx[b * NN + i]   = orig;
        sx[i] = x; sy[i] = y; sz[i] = z;
    }
    __syncthreads();

    // exact per-chunk AABBs (32 warps handle 64 chunks)
    const int wid  = threadIdx.x >> 5;
    const int lane = threadIdx.x & 31;
    for (int c = wid; c < NCHUNK; c += 32) {
        float x = sx[c * 32 + lane], y = sy[c * 32 + lane], z = sz[c * 32 + lane];
        float xl = x, xh = x, yl = y, yh = y, zl = z, zh = z;
#pragma unroll
        for (int o = 16; o; o >>= 1) {
            xl = fminf(xl, __shfl_xor_sync(FULLM, xl, o));
            xh = fmaxf(xh, __shfl_xor_sync(FULLM, xh, o));
            yl = fminf(yl, __shfl_xor_sync(FULLM, yl, o));
            yh = fmaxf(yh, __shfl_xor_sync(FULLM, yh, o));
            zl = fminf(zl, __shfl_xor_sync(FULLM, zl, o));
            zh = fmaxf(zh, __shfl_xor_sync(FULLM, zh, o));
        }
        if (lane == 0) {
            g_blo[b * NCHUNK + c] = make_float4(xl, yl, zl, 0.0f);
            g_bhi[b * NCHUNK + c] = make_float4(xh, yh, zh, 0.0f);
        }
    }
}

// ---------------------------------------------------------------------------
// Kernel 1: warp-per-query masked KNN over Morton chunks with AABB pruning.
// Own chunk: warp-bitonic full sort -> top-10 + tight tau. Masked chunks are
// scanned NEAREST-FIRST (above cown ascending, below descending) and each is
// re-tested against the CURRENT tau via its AABB min-d2 before scanning.
// Keys (bits(d2+1e-7)<<32)|orig_idx, exact stable top_k.
// ---------------------------------------------------------------------------
#define SCAN_CHUNK(c)                                                         \
    {                                                                         \
        const int i_ = (c) * 32 + lane;                                       \
        float4 p = sp[i_];                                                    \
        float dot = qx * p.x + qy * p.y + qz * p.z;                           \
        float d2f = (qw + p.w - 2.0f * dot) + 1e-7f;                          \
        unsigned du = __float_as_uint(d2f);                                   \
        bool pred = (d2f >= 0.1f) && (du <= tau);                             \
        unsigned m = __ballot_sync(FULLM, pred);                              \
        if (m) {                                                              \
            unsigned long long kk =                                           \
                ((unsigned long long)du << 32) | (unsigned)si[i_];            \
            do {                                                              \
                int s = __ffs(m) - 1;                                         \
                m &= m - 1;                                                   \
                unsigned long long k = __shfl_sync(FULLM, kk, s);             \
                unsigned long long up = __shfl_up_sync(FULLM, key, 1);        \
                bool cc = (k < key);                                          \
                unsigned long long ins = (lane == 0 || up <= k) ? k : up;     \
                key = cc ? ins : key;                                         \
            } while (m);                                                      \
            tau = __shfl_sync(FULLM, (unsigned)(key >> 32), 9);               \
        }                                                                     \
    }

// Re-test chunk against CURRENT tau using its AABB min-d2 (uniform branch).
// tau==MAX -> limf is NaN -> (mdc > NaN) false -> always scans (safe).
#define TRY_SCAN(c_)                                                          \
    {                                                                         \
        const int cc_ = (c_);                                                 \
        float mdsrc = (cc_ & 32) ? md1 : md0;                                 \
        float mdc = __shfl_sync(FULLM, mdsrc, cc_ & 31);                      \
        float limf = __uint_as_float(tau) + 1e-4f;                            \
        if (!(mdc > limf)) SCAN_CHUNK(cc_)                                    \
    }

__global__ void __launch_bounds__(512) knn_kernel(const float* __restrict__ src) {
    __shared__ float4 sp[NN];
    __shared__ int    si[NN];
    __shared__ float4 sblo[NCHUNK], sbhi[NCHUNK];
    const int b   = blockIdx.x >> 7;     // 128 blocks per batch, 16 warps each
    const int grp = blockIdx.x & 127;

    for (int i = threadIdx.x; i < NN; i += 512) {
        sp[i] = g_sorted[b * NN + i];
        si[i] = g_sidx[b * NN + i];
    }
    if (threadIdx.x < NCHUNK) {
        sblo[threadIdx.x] = g_blo[b * NCHUNK + threadIdx.x];
        sbhi[threadIdx.x] = g_bhi[b * NCHUNK + threadIdx.x];
    }
    __syncthreads();

    const int warp = threadIdx.x >> 5;
    const int lane = threadIdx.x & 31;
    const int sq   = grp * 16 + warp;    // sorted position of this query
    const int q    = si[sq];             // original index (output row)

    const float4 Q = sp[sq];
    const float qx = Q.x, qy = Q.y, qz = Q.z, qw = Q.w;

    unsigned long long key;
    unsigned tau;
    const int cown = sq >> 5;

    // ---- own (Morton-local) chunk: full warp bitonic sort -> top-10 + tau --
    {
        const int i_ = cown * 32 + lane;
        float4 p = sp[i_];
        float dot = qx * p.x + qy * p.y + qz * p.z;
        float d2f = (qw + p.w - 2.0f * dot) + 1e-7f;
        unsigned du = __float_as_uint(d2f);
        key = (d2f >= 0.1f)
                  ? (((unsigned long long)du << 32) | (unsigned)si[i_])
                  : ~0ULL;
#pragma unroll
        for (int k = 2; k <= 32; k <<= 1) {
#pragma unroll
            for (int j = k >> 1; j > 0; j >>= 1) {
                unsigned long long o = __shfl_xor_sync(FULLM, key, j);
                bool takeMin = (((lane & j) == 0) == ((lane & k) == 0));
                unsigned long long mn = (o < key) ? o : key;
                unsigned long long mx = (o < key) ? key : o;
                key = takeMin ? mn : mx;
            }
        }
        if (lane >= KK) key = ~0ULL;
        tau = __shfl_sync(FULLM, (unsigned)(key >> 32), 9);
    }

    // ---- AABB mask: chunks that can still contain a better neighbor ----
    const float INF = __int_as_float(0x7f800000);
    const float lim = ((tau == 0xFFFFFFFFu) ? INF : __uint_as_float(tau)) + 1e-4f;

    float md0, md1;
    {
        float4 lo = sblo[lane], hi = sbhi[lane];
        float dx = fmaxf(0.0f, fmaxf(lo.x - qx, qx - hi.x));
        float dy = fmaxf(0.0f, fmaxf(lo.y - qy, qy - hi.y));
        float dz = fmaxf(0.0f, fmaxf(lo.z - qz, qz - hi.z));
        md0 = dx * dx + dy * dy + dz * dz;
        lo = sblo[lane + 32]; hi = sbhi[lane + 32];
        dx = fmaxf(0.0f, fmaxf(lo.x - qx, qx - hi.x));
        dy = fmaxf(0.0f, fmaxf(lo.y - qy, qy - hi.y));
        dz = fmaxf(0.0f, fmaxf(lo.z - qz, qz - hi.z));
        md1 = dx * dx + dy * dy + dz * dz;
    }
    unsigned m1 = __ballot_sync(FULLM, md0 <= lim);
    unsigned m2 = __ballot_sync(FULLM, md1 <= lim);

    unsigned long long mask = ((unsigned long long)m2 << 32) | (unsigned long long)m1;
    mask &= ~(1ULL << cown);             // own chunk already processed

    // nearest-first: above cown ascending, below cown descending
    unsigned long long below = mask & ((1ULL << cown) - 1ULL);
    unsigned long long above = mask ^ below;

    while (above) {
        int c = __ffsll((long long)above) - 1;
        above &= above - 1;
        TRY_SCAN(c);
    }
    while (below) {
        int c = 63 - __clzll((long long)below);
        below ^= (1ULL << c);
        TRY_SCAN(c);
    }

    int* op = g_idx + ((size_t)(b * NN) + q) * KK;

    unsigned vm = __ballot_sync(FULLM, key != ~0ULL) & 0x3FFu;
    int cnt = __popc(vm);
    if (lane < cnt) op[lane] = (int)(unsigned)key;

    // Very rare: fewer than 10 valid neighbors total -> top_k pads with the
    // smallest masked ORIGINAL indices (all tied at -inf).
    if (cnt < KK && lane == 0) {
        const float* base = src + (size_t)b * 3 * NN;
        int slot = cnt;
        for (int i = 0; i < NN && slot < KK; i++) {
            float x = base[i], y = base[NN + i], z = base[2 * NN + i];
            float pw = x * x + y * y + z * z;
            float dot = qx * x + qy * y + qz * z;
            float d2f = (qw + pw - 2.0f * dot) + 1e-7f;
            if (!(d2f >= 0.1f)) op[slot++] = i;
        }
    }
}

// ---------------------------------------------------------------------------
// Kernel 2: 45 triangle pair losses per point, mean of sqrt of 10 smallest.
// Per-batch min via atomicMin; the LAST block of each batch (completion
// counter, broadcast via __syncthreads_or -> zero extra smem) computes the
// thresholded weights for the whole batch (fused epilogue).
// ---------------------------------------------------------------------------
__device__ __forceinline__ void sort3(float& a, float& b, float& c) {
    float t0 = fminf(a, b), t1 = fmaxf(a, b);
    float hi = fmaxf(t1, c);
    float mm = fminf(t1, c);
    float lo = fminf(t0, mm);
    float mi = fmaxf(t0, mm);
    a = lo; b = mi; c = hi;
}

#define K2_BLK 256
#define K2_BPB (NN / K2_BLK)     // 8 blocks per batch

__global__ void __launch_bounds__(K2_BLK) loss_kernel(const float* __restrict__ src,
                                                      const float* __restrict__ tgt,
                                                      float* __restrict__ out) {
    __shared__ float ssx[NN], ssy[NN], ssz[NN];
    __shared__ float stx[NN], sty[NN], stz[NN];
    const int b     = blockIdx.x / K2_BPB;
    const int chunk = blockIdx.x % K2_BPB;
    const float* sb = src + (size_t)b * 3 * NN;
    const float* tb = tgt + (size_t)b * 3 * NN;

    for (int i = threadIdx.x; i < NN; i += K2_BLK) {
        ssx[i] = sb[i]; ssy[i] = sb[NN + i]; ssz[i] = sb[2 * NN + i];
        stx[i] = tb[i]; sty[i] = tb[NN + i]; stz[i] = tb[2 * NN + i];
    }
    __syncthreads();

    const int n = chunk * K2_BLK + threadIdx.x;
    const int* nb = g_idx + ((size_t)(b * NN) + n) * KK;

    float px[KK + 1], py[KK + 1], pz[KK + 1];
    float tx[KK + 1], ty[KK + 1], tz[KK + 1];
    px[0] = ssx[n]; py[0] = ssy[n]; pz[0] = ssz[n];
    tx[0] = stx[n]; ty[0] = sty[n]; tz[0] = stz[n];
#pragma unroll
    for (int j = 0; j < KK; j++) {
        int m = nb[j];
        px[j + 1] = ssx[m]; py[j + 1] = ssy[m]; pz[j + 1] = ssz[m];
        tx[j + 1] = stx[m]; ty[j + 1] = sty[m]; tz[j + 1] = stz[m];
    }

    const float INF = __int_as_float(0x7f800000);
    float ls[KK];
#pragma unroll
    for (int j = 0; j < KK; j++) ls[j] = INF;
    float worst = INF;

#pragma unroll
    for (int a = 0; a < KK - 1; a++) {
#pragma unroll
        for (int c = a + 1; c < KK; c++) {
            const int ia = a + 1, ic = c + 1;
            float dx, dy, dz;
            dx = px[0] - px[ia]; dy = py[0] - py[ia]; dz = pz[0] - pz[ia];
            float s01 = dx * dx + dy * dy + dz * dz;
            dx = px[ia] - px[ic]; dy = py[ia] - py[ic]; dz = pz[ia] - pz[ic];
            float s12 = dx * dx + dy * dy + dz * dz;
            dx = px[0] - px[ic]; dy = py[0] - py[ic]; dz = pz[0] - pz[ic];
            float s02 = dx * dx + dy * dy + dz * dz;
            sort3(s01, s12, s02);
            dx = tx[0] - tx[ia]; dy = ty[0] - ty[ia]; dz = tz[0] - tz[ia];
            float t01 = dx * dx + dy * dy + dz * dz;
            dx = tx[ia] - tx[ic]; dy = ty[ia] - ty[ic]; dz = tz[ia] - tz[ic];
            float t12 = dx * dx + dy * dy + dz * dz;
            dx = tx[0] - tx[ic]; dy = ty[0] - ty[ic]; dz = tz[0] - tz[ic];
            float t02 = dx * dx + dy * dy + dz * dz;
            sort3(t01, t12, t02);
            t01 += 1e-6f; t12 += 1e-6f; t02 += 1e-6f;

            float n0 = s01 - t01, n1 = s12 - t12, n2 = s02 - t02;
            float num = n0 * n0 + n1 * n1 + n2 * n2;
            float p0 = s01 + t01, p1 = s12 + t12, p2 = s02 + t02;
            float den = p0 * p0 + p1 * p1 + p2 * p2;
            float L = num / den;

            if (L < worst) {
                float cd = L;
#pragma unroll
                for (int j = 0; j < KK; j++) {
                    if (cd < ls[j]) { float t = ls[j]; ls[j] = cd; cd = t; }
                }
                worst = ls[KK - 1];
            }
        }
    }

    float acc = 0.0f;
#pragma unroll
    for (int j = 0; j < KK; j++) acc += sqrtf(ls[j] + 1e-6f);
    float loss = acc * 0.1f;
    g_loss[b * NN + n] = loss;

    // per-batch min (nonneg floats: uint bit order == float order)
    float wm = loss;
#pragma unroll
    for (int o = 16; o; o >>= 1) wm = fminf(wm, __shfl_xor_sync(FULLM, wm, o));
    if ((threadIdx.x & 31) == 0) atomicMin(&g_min[b], __float_as_uint(wm));

    // make this block's g_loss stores + atomics globally visible
    __threadfence();

    int lastPred = 0;
    if (threadIdx.x == 0)
        lastPred = (atomicAdd(&g_cnt[b], 1) == K2_BPB - 1);
    // barrier + block-wide OR broadcast (no shared memory needed)
    if (__syncthreads_or(lastPred)) {
        __threadfence();   // acquire: prior blocks' g_loss/g_min visible
        const float bmin = __uint_as_float(g_min[b]);
        for (int i = threadIdx.x; i < NN; i += K2_BLK) {
            float x = g_loss[b * NN + i] - bmin;
            float w = 2.0f / (1.0f + expf(30.0f * x));
            out[b * NN + i] = (w > 0.6f) ? 1.0f : 0.0f;
        }
    }
}

// ---------------------------------------------------------------------------
extern "C" void kernel_launch(void* const* d_in, const int* in_sizes, int n_in,
                              void* d_out, int out_size) {
    const float* src = (const float*)d_in[0];
    const float* tgt = (const float*)d_in[1];
    float* out = (float*)d_out;

    sort_kernel<<<BB, 1024>>>(src);
    knn_kernel <<<BB * (NN / 16), 512>>>(src);
    loss_kernel<<<BB * K2_BPB, K2_BLK>>>(src, tgt, out);
}

// round 15
// speedup vs baseline: 1.1642x; 1.1642x over previous
#include <cuda_runtime.h>

#define BB 16
#define NN 2048
#define KK 10
#define FULLM 0xffffffffu
#define NCHUNK (NN / 32)          // 64

__device__ int      g_idx[BB * NN * KK];
__device__ float    g_loss[BB * NN];
__device__ float4   g_sorted[BB * NN];
__device__ int      g_sidx[BB * NN];
__device__ float4   g_blo[BB * NCHUNK];
__device__ float4   g_bhi[BB * NCHUNK];
__device__ unsigned g_min[BB];

__device__ __forceinline__ unsigned expand10(unsigned v) {
    v &= 1023u;
    v = (v | (v << 16)) & 0x030000FFu;
    v = (v | (v << 8))  & 0x0300F00Fu;
    v = (v | (v << 4))  & 0x030C30C3u;
    v = (v | (v << 2))  & 0x09249249u;
    return v;
}

// ---------------------------------------------------------------------------
// Kernel 0: per-batch HYBRID bitonic sort by Morton code (u64 = key<<32|idx).
// Stages with j<=32 run in registers via shfl (2 elems/thread, in-warp
// partners); only j>=64 stages use smem+barrier (15 of 66 stages).
// Emits sorted (x,y,z,|p|^2), original indices, exact per-chunk AABBs.
// ---------------------------------------------------------------------------
__global__ void __launch_bounds__(1024) sort_kernel(const float* __restrict__ src) {
    __shared__ unsigned long long a[NN];              // 16 KB
    __shared__ float sx[NN], sy[NN], sz[NN];          // 24 KB
    const int b = blockIdx.x;
    const float* base = src + (size_t)b * 3 * NN;
    if (threadIdx.x == 0) g_min[b] = 0x7f800000u;     // +inf bits

    const int tid  = threadIdx.x;
    const int lane = tid & 31;

    for (int i = tid; i < NN; i += 1024) {
        float x = base[i], y = base[NN + i], z = base[2 * NN + i];
        int qxi = (int)((x + 8.0f) * 64.0f);
        int qyi = (int)((y + 8.0f) * 64.0f);
        int qzi = (int)((z + 8.0f) * 64.0f);
        qxi = min(max(qxi, 0), 1023);
        qyi = min(max(qyi, 0), 1023);
        qzi = min(max(qzi, 0), 1023);
        unsigned mk = (expand10((unsigned)qxi) << 2) |
                      (expand10((unsigned)qyi) << 1) |
                       expand10((unsigned)qzi);
        a[i] = ((unsigned long long)mk << 32) | (unsigned)i;
    }
    __syncthreads();

    for (int k = 2; k <= NN; k <<= 1) {
        // smem stages (cross-warp): j >= 64
        for (int j = k >> 1; j >= 64; j >>= 1) {
            const int i   = 2 * tid - (tid & (j - 1));
            const int ixj = i + j;
            const bool up = ((i & k) == 0);
            unsigned long long x = a[i], y = a[ixj];
            if ((x > y) == up) { a[i] = y; a[ixj] = x; }
            __syncthreads();
        }
        // register session: j = min(k/2, 32) .. 1 (in-warp shuffles)
        unsigned long long e0 = a[2 * tid], e1 = a[2 * tid + 1];
        const bool up = (((2 * tid) & k) == 0);
        for (int j = (k >> 1) < 32 ? (k >> 1) : 32; j >= 2; j >>= 1) {
            const int h = j >> 1;                     // 1..16: in-warp
            unsigned long long o0 = __shfl_xor_sync(FULLM, e0, h);
            unsigned long long o1 = __shfl_xor_sync(FULLM, e1, h);
            const bool keepMin = (((lane & h) == 0) == up);
            e0 = keepMin ? (e0 < o0 ? e0 : o0) : (e0 < o0 ? o0 : e0);
            e1 = keepMin ? (e1 < o1 ? e1 : o1) : (e1 < o1 ? o1 : e1);
        }
        // j == 1: in-thread pair
        if ((e0 > e1) == up) { unsigned long long t = e0; e0 = e1; e1 = t; }
        a[2 * tid]     = e0;
        a[2 * tid + 1] = e1;
        __syncthreads();
    }

    for (int i = tid; i < NN; i += 1024) {
        int orig = (int)(unsigned)a[i];
        float x = base[orig];
        float y = base[NN + orig];
        float z = base[2 * NN + orig];
        g_sorted[b * NN + i] = make_float4(x, y, z, x * x + y * y + z * z);
        g_sidx[b * NN + i]   = orig;
        sx[i] = x; sy[i] = y; sz[i] = z;
    }
    __syncthreads();

    // exact per-chunk AABBs (32 warps handle 64 chunks)
    const int wid = tid >> 5;
    for (int c = wid; c < NCHUNK; c += 32) {
        float x = sx[c * 32 + lane], y = sy[c * 32 + lane], z = sz[c * 32 + lane];
        float xl = x, xh = x, yl = y, yh = y, zl = z, zh = z;
#pragma unroll
        for (int o = 16; o; o >>= 1) {
            xl = fminf(xl, __shfl_xor_sync(FULLM, xl, o));
            xh = fmaxf(xh, __shfl_xor_sync(FULLM, xh, o));
            yl = fminf(yl, __shfl_xor_sync(FULLM, yl, o));
            yh = fmaxf(yh, __shfl_xor_sync(FULLM, yh, o));
            zl = fminf(zl, __shfl_xor_sync(FULLM, zl, o));
            zh = fmaxf(zh, __shfl_xor_sync(FULLM, zh, o));
        }
        if (lane == 0) {
            g_blo[b * NCHUNK + c] = make_float4(xl, yl, zl, 0.0f);
            g_bhi[b * NCHUNK + c] = make_float4(xh, yh, zh, 0.0f);
        }
    }
}

// ---------------------------------------------------------------------------
// Kernel 1: warp-per-query masked KNN over Morton chunks with AABB pruning.
// (byte-identical logic to the 96.3us R12 version)
// ---------------------------------------------------------------------------
#define SCAN_CHUNK(c)                                                         \
    {                                                                         \
        const int i_ = (c) * 32 + lane;                                       \
        float4 p = sp[i_];                                                    \
        float dot = qx * p.x + qy * p.y + qz * p.z;                           \
        float d2f = (qw + p.w - 2.0f * dot) + 1e-7f;                          \
        unsigned du = __float_as_uint(d2f);                                   \
        bool pred = (d2f >= 0.1f) && (du <= tau);                             \
        unsigned m = __ballot_sync(FULLM, pred);                              \
        if (m) {                                                              \
            unsigned long long kk =                                           \
                ((unsigned long long)du << 32) | (unsigned)si[i_];            \
            do {                                                              \
                int s = __ffs(m) - 1;                                         \
                m &= m - 1;                                                   \
                unsigned long long k = __shfl_sync(FULLM, kk, s);             \
                unsigned long long up = __shfl_up_sync(FULLM, key, 1);        \
                bool cc = (k < key);                                          \
                unsigned long long ins = (lane == 0 || up <= k) ? k : up;     \
                key = cc ? ins : key;                                         \
            } while (m);                                                      \
            tau = __shfl_sync(FULLM, (unsigned)(key >> 32), 9);               \
        }                                                                     \
    }

__global__ void __launch_bounds__(512) knn_kernel(const float* __restrict__ src) {
    __shared__ float4 sp[NN];
    __shared__ int    si[NN];
    __shared__ float4 sblo[NCHUNK], sbhi[NCHUNK];
    const int b   = blockIdx.x >> 7;     // 128 blocks per batch, 16 warps each
    const int grp = blockIdx.x & 127;

    for (int i = threadIdx.x; i < NN; i += 512) {
        sp[i] = g_sorted[b * NN + i];
        si[i] = g_sidx[b * NN + i];
    }
    if (threadIdx.x < NCHUNK) {
        sblo[threadIdx.x] = g_blo[b * NCHUNK + threadIdx.x];
        sbhi[threadIdx.x] = g_bhi[b * NCHUNK + threadIdx.x];
    }
    __syncthreads();

    const int warp = threadIdx.x >> 5;
    const int lane = threadIdx.x & 31;
    const int sq   = grp * 16 + warp;    // sorted position of this query
    const int q    = si[sq];             // original index (output row)

    const float4 Q = sp[sq];
    const float qx = Q.x, qy = Q.y, qz = Q.z, qw = Q.w;

    unsigned long long key;
    unsigned tau;
    const int cown = sq >> 5;

    // ---- own (Morton-local) chunk: full warp bitonic sort -> top-10 + tau --
    {
        const int i_ = cown * 32 + lane;
        float4 p = sp[i_];
        float dot = qx * p.x + qy * p.y + qz * p.z;
        float d2f = (qw + p.w - 2.0f * dot) + 1e-7f;
        unsigned du = __float_as_uint(d2f);
        key = (d2f >= 0.1f)
                  ? (((unsigned long long)du << 32) | (unsigned)si[i_])
                  : ~0ULL;
#pragma unroll
        for (int k = 2; k <= 32; k <<= 1) {
#pragma unroll
            for (int j = k >> 1; j > 0; j >>= 1) {
                unsigned long long o = __shfl_xor_sync(FULLM, key, j);
                bool takeMin = (((lane & j) == 0) == ((lane & k) == 0));
                unsigned long long mn = (o < key) ? o : key;
                unsigned long long mx = (o < key) ? key : o;
                key = takeMin ? mn : mx;
            }
        }
        if (lane >= KK) key = ~0ULL;
        tau = __shfl_sync(FULLM, (unsigned)(key >> 32), 9);
    }

    // ---- AABB mask: chunks that can still contain a better neighbor ----
    const float INF = __int_as_float(0x7f800000);
    const float lim = ((tau == 0xFFFFFFFFu) ? INF : __uint_as_float(tau)) + 1e-4f;

    float md0, md1;
    {
        float4 lo = sblo[lane], hi = sbhi[lane];
        float dx = fmaxf(0.0f, fmaxf(lo.x - qx, qx - hi.x));
        float dy = fmaxf(0.0f, fmaxf(lo.y - qy, qy - hi.y));
        float dz = fmaxf(0.0f, fmaxf(lo.z - qz, qz - hi.z));
        md0 = dx * dx + dy * dy + dz * dz;
        lo = sblo[lane + 32]; hi = sbhi[lane + 32];
        dx = fmaxf(0.0f, fmaxf(lo.x - qx, qx - hi.x));
        dy = fmaxf(0.0f, fmaxf(lo.y - qy, qy - hi.y));
        dz = fmaxf(0.0f, fmaxf(lo.z - qz, qz - hi.z));
        md1 = dx * dx + dy * dy + dz * dz;
    }
    unsigned m1 = __ballot_sync(FULLM, md0 <= lim);
    unsigned m2 = __ballot_sync(FULLM, md1 <= lim);
    if (cown < 32) m1 &= ~(1u << cown); else m2 &= ~(1u << (cown - 32));

    while (m1) {
        int c = __ffs(m1) - 1;
        m1 &= m1 - 1;
        SCAN_CHUNK(c);
    }
    while (m2) {
        int c = 32 + __ffs(m2) - 1;
        m2 &= m2 - 1;
        SCAN_CHUNK(c);
    }

    int* op = g_idx + ((size_t)(b * NN) + q) * KK;

    unsigned vm = __ballot_sync(FULLM, key != ~0ULL) & 0x3FFu;
    int cnt = __popc(vm);
    if (lane < cnt) op[lane] = (int)(unsigned)key;

    // Very rare: fewer than 10 valid neighbors total -> top_k pads with the
    // smallest masked ORIGINAL indices (all tied at -inf).
    if (cnt < KK && lane == 0) {
        const float* base = src + (size_t)b * 3 * NN;
        int slot = cnt;
        for (int i = 0; i < NN && slot < KK; i++) {
            float x = base[i], y = base[NN + i], z = base[2 * NN + i];
            float pw = x * x + y * y + z * z;
            float dot = qx * x + qy * y + qz * z;
            float d2f = (qw + pw - 2.0f * dot) + 1e-7f;
            if (!(d2f >= 0.1f)) op[slot++] = i;
        }
    }
}

// ---------------------------------------------------------------------------
// Kernel 2: 45 triangle pair losses per point, mean of sqrt of 10 smallest.
// Also reduces the per-batch min into g_min via atomicMin on uint bits.
// ---------------------------------------------------------------------------
__device__ __forceinline__ void sort3(float& a, float& b, float& c) {
    float t0 = fminf(a, b), t1 = fmaxf(a, b);
    float hi = fmaxf(t1, c);
    float mm = fminf(t1, c);
    float lo = fminf(t0, mm);
    float mi = fmaxf(t0, mm);
    a = lo; b = mi; c = hi;
}

#define K2_BLK 256

__global__ void __launch_bounds__(K2_BLK) loss_kernel(const float* __restrict__ src,
                                                      const float* __restrict__ tgt) {
    __shared__ float ssx[NN], ssy[NN], ssz[NN];
    __shared__ float stx[NN], sty[NN], stz[NN];
    const int blocksPerB = NN / K2_BLK;
    const int b     = blockIdx.x / blocksPerB;
    const int chunk = blockIdx.x % blocksPerB;
    const float* sb = src + (size_t)b * 3 * NN;
    const float* tb = tgt + (size_t)b * 3 * NN;

    for (int i = threadIdx.x; i < NN; i += K2_BLK) {
        ssx[i] = sb[i]; ssy[i] = sb[NN + i]; ssz[i] = sb[2 * NN + i];
        stx[i] = tb[i]; sty[i] = tb[NN + i]; stz[i] = tb[2 * NN + i];
    }
    __syncthreads();

    const int n = chunk * K2_BLK + threadIdx.x;
    const int* nb = g_idx + ((size_t)(b * NN) + n) * KK;

    float px[KK + 1], py[KK + 1], pz[KK + 1];
    float tx[KK + 1], ty[KK + 1], tz[KK + 1];
    px[0] = ssx[n]; py[0] = ssy[n]; pz[0] = ssz[n];
    tx[0] = stx[n]; ty[0] = sty[n]; tz[0] = stz[n];
#pragma unroll
    for (int j = 0; j < KK; j++) {
        int m = nb[j];
        px[j + 1] = ssx[m]; py[j + 1] = ssy[m]; pz[j + 1] = ssz[m];
        tx[j + 1] = stx[m]; ty[j + 1] = sty[m]; tz[j + 1] = stz[m];
    }

    const float INF = __int_as_float(0x7f800000);
    float ls[KK];
#pragma unroll
    for (int j = 0; j < KK; j++) ls[j] = INF;
    float worst = INF;

#pragma unroll
    for (int a = 0; a < KK - 1; a++) {
#pragma unroll
        for (int c = a + 1; c < KK; c++) {
            const int ia = a + 1, ic = c + 1;
            float dx, dy, dz;
            dx = px[0] - px[ia]; dy = py[0] - py[ia]; dz = pz[0] - pz[ia];
            float s01 = dx * dx + dy * dy + dz * dz;
            dx = px[ia] - px[ic]; dy = py[ia] - py[ic]; dz = pz[ia] - pz[ic];
            float s12 = dx * dx + dy * dy + dz * dz;
            dx = px[0] - px[ic]; dy = py[0] - py[ic]; dz = pz[0] - pz[ic];
            float s02 = dx * dx + dy * dy + dz * dz;
            sort3(s01, s12, s02);
            dx = tx[0] - tx[ia]; dy = ty[0] - ty[ia]; dz = tz[0] - tz[ia];
            float t01 = dx * dx + dy * dy + dz * dz;
            dx = tx[ia] - tx[ic]; dy = ty[ia] - ty[ic]; dz = tz[ia] - tz[ic];
            float t12 = dx * dx + dy * dy + dz * dz;
            dx = tx[0] - tx[ic]; dy = ty[0] - ty[ic]; dz = tz[0] - tz[ic];
            float t02 = dx * dx + dy * dy + dz * dz;
            sort3(t01, t12, t02);
            t01 += 1e-6f; t12 += 1e-6f; t02 += 1e-6f;

            float n0 = s01 - t01, n1 = s12 - t12, n2 = s02 - t02;
            float num = n0 * n0 + n1 * n1 + n2 * n2;
            float p0 = s01 + t01, p1 = s12 + t12, p2 = s02 + t02;
            float den = p0 * p0 + p1 * p1 + p2 * p2;
            float L = num / den;

            if (L < worst) {
                float cd = L;
#pragma unroll
                for (int j = 0; j < KK; j++) {
                    if (cd < ls[j]) { float t = ls[j]; ls[j] = cd; cd = t; }
                }
                worst = ls[KK - 1];
            }
        }
    }

    float acc = 0.0f;
#pragma unroll
    for (int j = 0; j < KK; j++) acc += sqrtf(ls[j] + 1e-6f);
    float loss = acc * 0.1f;
    g_loss[b * NN + n] = loss;

    // block-level min -> one atomic per warp (nonneg floats: bits are ordered)
    float wm = loss;
#pragma unroll
    for (int o = 16; o; o >>= 1) wm = fminf(wm, __shfl_xor_sync(FULLM, wm, o));
    if ((threadIdx.x & 31) == 0) atomicMin(&g_min[b], __float_as_uint(wm));
}

// ---------------------------------------------------------------------------
// Kernel 3: threshold pass (min already in g_min)
// ---------------------------------------------------------------------------
__global__ void __launch_bounds__(256) weight_kernel(float* __restrict__ out) {
    const int b = blockIdx.x >> 3;           // 8 blocks per batch
    const int i = (blockIdx.x & 7) * 256 + threadIdx.x;
    const float bmin = __uint_as_float(g_min[b]);
    float x = g_loss[b * NN + i] - bmin;
    float w = 2.0f / (1.0f + expf(30.0f * x));
    out[b * NN + i] = (w > 0.6f) ? 1.0f : 0.0f;
}

// ---------------------------------------------------------------------------
extern "C" void kernel_launch(void* const* d_in, const int* in_sizes, int n_in,
                              void* d_out, int out_size) {
    const float* src = (const float*)d_in[0];
    const float* tgt = (const float*)d_in[1];
    float* out = (float*)d_out;

    sort_kernel  <<<BB, 1024>>>(src);
    knn_kernel   <<<BB * (NN / 16), 512>>>(src);
    loss_kernel  <<<BB * (NN / K2_BLK), K2_BLK>>>(src, tgt);
    weight_kernel<<<BB * 8, 256>>>(out);
}